// round 12
// baseline (speedup 1.0000x reference)
#include <cuda_runtime.h>
#include <cuda_bf16.h>

// CWTConv2D: quantized 3x3 valid conv.
// out[b,i,j,f] = relu( sum_{u,v} round(x[b,i+u,j+v]) * clip(round(kw[f,2-u,2-v]),-1,1)
//                      + round(bias[f]) )
// x (32,512,512) f32, kw (32,3,3) f32, bias (32,) f32 -> out (32,510,510,32) f32 NHWC.
//
// Design (R7): warp = 1 output row x 128 cols, lane = filter channel.
//  - div-free vectorized smem fill (float4 LDG/STS, shift-based indexing)
//  - 4 output cols per inner iteration; sliding window holds cols j..j+3,
//    loads cols j+4..j+7 as one aligned LDS.128 per row (3 rows)
//  - per 4 pixels (512 B stored): 3 LDS.128 + 36 FFMA + 4 FMNMX + 4 STG
//  - __launch_bounds__(256,6): <=42 regs -> 48 warps/SM (75% occ)

#define BATCH   32
#define HW      512
#define OHW     510
#define NF      32
#define TR      8                    // output rows per block (1 per warp)
#define TC      128                  // output cols per block
#define SM_ROWS (TR + 2)             // 10 input rows
#define SM_STRIDE 132                // 130 needed cols + pad; mult of 4 -> f4 aligned

__global__ __launch_bounds__(256, 6)
void cwtconv2d_kernel(const float* __restrict__ x,
                      const float* __restrict__ kw,
                      const float* __restrict__ bias,
                      float* __restrict__ out)
{
    __shared__ float sx[SM_ROWS * SM_STRIDE];

    const int b   = blockIdx.z;
    const int gr0 = blockIdx.y * TR;
    const int gc0 = blockIdx.x * TC;
    const int tid  = threadIdx.x;
    const int lane = tid & 31;       // filter index
    const int wrp  = tid >> 5;       // output row within tile

    // per-lane weights: quantize + double flip (raster-order dot with x patch)
    float wf0, wf1, wf2, wf3, wf4, wf5, wf6, wf7, wf8;
    {
        const float* kp = kw + lane * 9;
        #define QW(i) fminf(fmaxf(rintf(__ldg(&kp[8 - (i)])), -1.0f), 1.0f)
        wf0 = QW(0); wf1 = QW(1); wf2 = QW(2);
        wf3 = QW(3); wf4 = QW(4); wf5 = QW(5);
        wf6 = QW(6); wf7 = QW(7); wf8 = QW(8);
        #undef QW
    }
    const float bia = rintf(__ldg(&bias[lane]));

    // ---- div-free vectorized fill: 10 rows x 32 float4 tasks (cols 0..127) ----
    // cols gc0..gc0+127 are always in-bounds (gc0 <= 384); only rows need guards.
    const float* xb = x + (size_t)b * HW * HW;
    #pragma unroll
    for (int t = tid; t < SM_ROWS * 32; t += 256) {   // 320 tasks
        int r = t >> 5;
        int k = (t & 31) << 2;
        int gr = gr0 + r;
        float4 v = make_float4(0.f, 0.f, 0.f, 0.f);
        if (gr < HW)
            v = *(const float4*)&xb[gr * HW + gc0 + k];
        v.x = rintf(v.x); v.y = rintf(v.y); v.z = rintf(v.z); v.w = rintf(v.w);
        *(float4*)&sx[r * SM_STRIDE + k] = v;
    }
    // tail: tile cols 128..131 (col 130/131 loaded by last LDS.128 but unused)
    if (tid < SM_ROWS * 4) {         // 40 threads
        int r = tid >> 2;
        int c = 128 + (tid & 3);
        int gr = gr0 + r;
        int gc = gc0 + c;
        float v = 0.0f;
        if (gr < HW && gc < HW) v = rintf(xb[gr * HW + gc]);
        sx[r * SM_STRIDE + c] = v;
    }
    __syncthreads();

    const int i = gr0 + wrp;
    if (i >= OHW) return;

    int jmax = OHW - gc0;            // 128,128,128,126
    if (jmax > TC) jmax = TC;

    const float* s0 = &sx[wrp * SM_STRIDE];

    // held window: cols j..j+3 for the 3 input rows
    float4 H0 = *(const float4*)&s0[0];
    float4 H1 = *(const float4*)&s0[SM_STRIDE];
    float4 H2 = *(const float4*)&s0[2 * SM_STRIDE];

    float* op = out + (((size_t)b * OHW + i) * OHW + gc0) * NF + lane;

    #pragma unroll 2
    for (int j = 0; j < jmax; j += 4) {
        // next 4 cols per row (aligned LDS.128; j+4 <= 128 -> within 132-col tile)
        float4 N0 = *(const float4*)&s0[j + 4];
        float4 N1 = *(const float4*)&s0[SM_STRIDE + j + 4];
        float4 N2 = *(const float4*)&s0[2 * SM_STRIDE + j + 4];

        float a0 = bia, a1 = bia, a2 = bia, a3 = bia;

        // row 0 taps (wf0..wf2)
        a0 = fmaf(H0.x, wf0, a0); a0 = fmaf(H0.y, wf1, a0); a0 = fmaf(H0.z, wf2, a0);
        a1 = fmaf(H0.y, wf0, a1); a1 = fmaf(H0.z, wf1, a1); a1 = fmaf(H0.w, wf2, a1);
        a2 = fmaf(H0.z, wf0, a2); a2 = fmaf(H0.w, wf1, a2); a2 = fmaf(N0.x, wf2, a2);
        a3 = fmaf(H0.w, wf0, a3); a3 = fmaf(N0.x, wf1, a3); a3 = fmaf(N0.y, wf2, a3);
        // row 1 taps (wf3..wf5)
        a0 = fmaf(H1.x, wf3, a0); a0 = fmaf(H1.y, wf4, a0); a0 = fmaf(H1.z, wf5, a0);
        a1 = fmaf(H1.y, wf3, a1); a1 = fmaf(H1.z, wf4, a1); a1 = fmaf(H1.w, wf5, a1);
        a2 = fmaf(H1.z, wf3, a2); a2 = fmaf(H1.w, wf4, a2); a2 = fmaf(N1.x, wf5, a2);
        a3 = fmaf(H1.w, wf3, a3); a3 = fmaf(N1.x, wf4, a3); a3 = fmaf(N1.y, wf5, a3);
        // row 2 taps (wf6..wf8)
        a0 = fmaf(H2.x, wf6, a0); a0 = fmaf(H2.y, wf7, a0); a0 = fmaf(H2.z, wf8, a0);
        a1 = fmaf(H2.y, wf6, a1); a1 = fmaf(H2.z, wf7, a1); a1 = fmaf(H2.w, wf8, a1);
        a2 = fmaf(H2.z, wf6, a2); a2 = fmaf(H2.w, wf7, a2); a2 = fmaf(N2.x, wf8, a2);
        a3 = fmaf(H2.w, wf6, a3); a3 = fmaf(N2.x, wf7, a3); a3 = fmaf(N2.y, wf8, a3);

        if (j + 4 <= jmax) {
            // fast path (all blocks except the last column-block's last iter)
            op[0 * NF] = fmaxf(a0, 0.0f);
            op[1 * NF] = fmaxf(a1, 0.0f);
            op[2 * NF] = fmaxf(a2, 0.0f);
            op[3 * NF] = fmaxf(a3, 0.0f);
        } else {
            if (j + 0 < jmax) op[0 * NF] = fmaxf(a0, 0.0f);
            if (j + 1 < jmax) op[1 * NF] = fmaxf(a1, 0.0f);
            if (j + 2 < jmax) op[2 * NF] = fmaxf(a2, 0.0f);
            if (j + 3 < jmax) op[3 * NF] = fmaxf(a3, 0.0f);
        }
        op += 4 * NF;

        // slide window by 4: full replacement -> register rotation under unroll
        H0 = N0; H1 = N1; H2 = N2;
    }
}

extern "C" void kernel_launch(void* const* d_in, const int* in_sizes, int n_in,
                              void* d_out, int out_size)
{
    const float* x    = (const float*)d_in[0];
    const float* kw   = (const float*)d_in[1];
    const float* bias = (const float*)d_in[2];
    float* out = (float*)d_out;

    dim3 grid((OHW + TC - 1) / TC,   // 4
              (OHW + TR - 1) / TR,   // 64
              BATCH);                // 32 -> 8192 blocks
    cwtconv2d_kernel<<<grid, 256>>>(x, kw, bias, out);
}

// round 13
// speedup vs baseline: 1.0509x; 1.0509x over previous
#include <cuda_runtime.h>
#include <cuda_bf16.h>

// CWTConv2D: quantized 3x3 valid conv.
// out[b,i,j,f] = relu( sum_{u,v} round(x[b,i+u,j+v]) * clip(round(kw[f,2-u,2-v]),-1,1)
//                      + round(bias[f]) )
// x (32,512,512) f32, kw (32,3,3) f32, bias (32,) f32 -> out (32,510,510,32) f32 NHWC.
//
// R13 design: warp = 2 output rows x 64 cols, lane = filter channel.
//  - tile 16 rows x 64 cols per 256-thread block (halo ratio 1.16)
//  - 4 output cols x 2 rows per inner iteration; 4-row sliding window,
//    4 aligned LDS.128 per iteration (0.5 LDS-wavefront / pixel, was 0.75)
//  - per 8 px (1024 B stored): 4 LDS.128 + 72 FFMA + 8 FMNMX + 8 STG.cs
//  - streaming stores (__stcs): output never re-read, evict-first in L2

#define BATCH   32
#define HW      512
#define OHW     510
#define NF      32
#define TRW     2                    // output rows per warp
#define TR      16                   // output rows per block (8 warps x 2)
#define TC      64                   // output cols per block
#define SM_ROWS (TR + 2)             // 18 input rows
#define SM_STRIDE 68                 // 66 needed cols + pad; 68*4B = 272B (16B mult)

__global__ __launch_bounds__(256, 4)
void cwtconv2d_kernel(const float* __restrict__ x,
                      const float* __restrict__ kw,
                      const float* __restrict__ bias,
                      float* __restrict__ out)
{
    __shared__ float sx[SM_ROWS * SM_STRIDE];

    const int b   = blockIdx.z;
    const int gr0 = blockIdx.y * TR;
    const int gc0 = blockIdx.x * TC;
    const int tid  = threadIdx.x;
    const int lane = tid & 31;       // filter index
    const int wrp  = tid >> 5;

    // per-lane weights: quantize + double flip (raster-order dot with x patch)
    float wf0, wf1, wf2, wf3, wf4, wf5, wf6, wf7, wf8;
    {
        const float* kp = kw + lane * 9;
        #define QW(i) fminf(fmaxf(rintf(__ldg(&kp[8 - (i)])), -1.0f), 1.0f)
        wf0 = QW(0); wf1 = QW(1); wf2 = QW(2);
        wf3 = QW(3); wf4 = QW(4); wf5 = QW(5);
        wf6 = QW(6); wf7 = QW(7); wf8 = QW(8);
        #undef QW
    }
    const float bia = rintf(__ldg(&bias[lane]));

    // ---- div-free vectorized fill ----
    // main: 18 rows x 16 float4 tasks (cols 0..63). gc0+63 <= 511 always ->
    // only rows need guards. 288 tasks over 256 threads.
    const float* xb = x + (size_t)b * HW * HW;
    #pragma unroll
    for (int t = tid; t < SM_ROWS * 16; t += 256) {
        int r = t >> 4;
        int k = (t & 15) << 2;
        int gr = gr0 + r;
        float4 v = make_float4(0.f, 0.f, 0.f, 0.f);
        if (gr < HW)
            v = *(const float4*)&xb[gr * HW + gc0 + k];
        v.x = rintf(v.x); v.y = rintf(v.y); v.z = rintf(v.z); v.w = rintf(v.w);
        *(float4*)&sx[r * SM_STRIDE + k] = v;
    }
    // tail: tile cols 64..67 (row+col guarded; 72 threads)
    if (tid < SM_ROWS * 4) {
        int r = tid >> 2;
        int c = 64 + (tid & 3);
        int gr = gr0 + r;
        int gc = gc0 + c;
        float v = 0.0f;
        if (gr < HW && gc < HW) v = rintf(xb[gr * HW + gc]);
        sx[r * SM_STRIDE + c] = v;
    }
    __syncthreads();

    const int r0 = wrp * TRW;        // warp's first output row within tile
    const int i0 = gr0 + r0;
    const bool ok0 = (i0     < OHW);
    const bool ok1 = (i0 + 1 < OHW);
    if (!ok0) return;                // rows are ordered: !ok0 implies !ok1

    int jmax = OHW - gc0;            // 64 except last col block: 62
    if (jmax > TC) jmax = TC;

    const float* s0 = &sx[r0 * SM_STRIDE];

    // held window: cols j..j+3 for the 4 input rows
    float4 H0 = *(const float4*)&s0[0 * SM_STRIDE];
    float4 H1 = *(const float4*)&s0[1 * SM_STRIDE];
    float4 H2 = *(const float4*)&s0[2 * SM_STRIDE];
    float4 H3 = *(const float4*)&s0[3 * SM_STRIDE];

    float* op0 = out + (((size_t)b * OHW + i0    ) * OHW + gc0) * NF + lane;
    float* op1 = out + (((size_t)b * OHW + i0 + 1) * OHW + gc0) * NF + lane;

    #pragma unroll 2
    for (int j = 0; j < jmax; j += 4) {
        // next 4 cols for the 4 window rows (aligned LDS.128, broadcast)
        float4 N0 = *(const float4*)&s0[0 * SM_STRIDE + j + 4];
        float4 N1 = *(const float4*)&s0[1 * SM_STRIDE + j + 4];
        float4 N2 = *(const float4*)&s0[2 * SM_STRIDE + j + 4];
        float4 N3 = *(const float4*)&s0[3 * SM_STRIDE + j + 4];

        float a00 = bia, a01 = bia, a02 = bia, a03 = bia;  // out row i0
        float a10 = bia, a11 = bia, a12 = bia, a13 = bia;  // out row i0+1

        // ---- out row 0: window rows H0,H1,H2 ----
        a00 = fmaf(H0.x, wf0, a00); a00 = fmaf(H0.y, wf1, a00); a00 = fmaf(H0.z, wf2, a00);
        a01 = fmaf(H0.y, wf0, a01); a01 = fmaf(H0.z, wf1, a01); a01 = fmaf(H0.w, wf2, a01);
        a02 = fmaf(H0.z, wf0, a02); a02 = fmaf(H0.w, wf1, a02); a02 = fmaf(N0.x, wf2, a02);
        a03 = fmaf(H0.w, wf0, a03); a03 = fmaf(N0.x, wf1, a03); a03 = fmaf(N0.y, wf2, a03);

        a00 = fmaf(H1.x, wf3, a00); a00 = fmaf(H1.y, wf4, a00); a00 = fmaf(H1.z, wf5, a00);
        a01 = fmaf(H1.y, wf3, a01); a01 = fmaf(H1.z, wf4, a01); a01 = fmaf(H1.w, wf5, a01);
        a02 = fmaf(H1.z, wf3, a02); a02 = fmaf(H1.w, wf4, a02); a02 = fmaf(N1.x, wf5, a02);
        a03 = fmaf(H1.w, wf3, a03); a03 = fmaf(N1.x, wf4, a03); a03 = fmaf(N1.y, wf5, a03);

        a00 = fmaf(H2.x, wf6, a00); a00 = fmaf(H2.y, wf7, a00); a00 = fmaf(H2.z, wf8, a00);
        a01 = fmaf(H2.y, wf6, a01); a01 = fmaf(H2.z, wf7, a01); a01 = fmaf(H2.w, wf8, a01);
        a02 = fmaf(H2.z, wf6, a02); a02 = fmaf(H2.w, wf7, a02); a02 = fmaf(N2.x, wf8, a02);
        a03 = fmaf(H2.w, wf6, a03); a03 = fmaf(N2.x, wf7, a03); a03 = fmaf(N2.y, wf8, a03);

        // ---- out row 1: window rows H1,H2,H3 ----
        a10 = fmaf(H1.x, wf0, a10); a10 = fmaf(H1.y, wf1, a10); a10 = fmaf(H1.z, wf2, a10);
        a11 = fmaf(H1.y, wf0, a11); a11 = fmaf(H1.z, wf1, a11); a11 = fmaf(H1.w, wf2, a11);
        a12 = fmaf(H1.z, wf0, a12); a12 = fmaf(H1.w, wf1, a12); a12 = fmaf(N1.x, wf2, a12);
        a13 = fmaf(H1.w, wf0, a13); a13 = fmaf(N1.x, wf1, a13); a13 = fmaf(N1.y, wf2, a13);

        a10 = fmaf(H2.x, wf3, a10); a10 = fmaf(H2.y, wf4, a10); a10 = fmaf(H2.z, wf5, a10);
        a11 = fmaf(H2.y, wf3, a11); a11 = fmaf(H2.z, wf4, a11); a11 = fmaf(H2.w, wf5, a11);
        a12 = fmaf(H2.z, wf3, a12); a12 = fmaf(H2.w, wf4, a12); a12 = fmaf(N2.x, wf5, a12);
        a13 = fmaf(H2.w, wf3, a13); a13 = fmaf(N2.x, wf4, a13); a13 = fmaf(N2.y, wf5, a13);

        a10 = fmaf(H3.x, wf6, a10); a10 = fmaf(H3.y, wf7, a10); a10 = fmaf(H3.z, wf8, a10);
        a11 = fmaf(H3.y, wf6, a11); a11 = fmaf(H3.z, wf7, a11); a11 = fmaf(H3.w, wf8, a11);
        a12 = fmaf(H3.z, wf6, a12); a12 = fmaf(H3.w, wf7, a12); a12 = fmaf(N3.x, wf8, a12);
        a13 = fmaf(H3.w, wf6, a13); a13 = fmaf(N3.x, wf7, a13); a13 = fmaf(N3.y, wf8, a13);

        if (j + 4 <= jmax) {
            // fast path: all iterations except the last of the last col block
            __stcs(&op0[0 * NF], fmaxf(a00, 0.0f));
            __stcs(&op0[1 * NF], fmaxf(a01, 0.0f));
            __stcs(&op0[2 * NF], fmaxf(a02, 0.0f));
            __stcs(&op0[3 * NF], fmaxf(a03, 0.0f));
            if (ok1) {
                __stcs(&op1[0 * NF], fmaxf(a10, 0.0f));
                __stcs(&op1[1 * NF], fmaxf(a11, 0.0f));
                __stcs(&op1[2 * NF], fmaxf(a12, 0.0f));
                __stcs(&op1[3 * NF], fmaxf(a13, 0.0f));
            }
        } else {
            if (j + 0 < jmax) { __stcs(&op0[0 * NF], fmaxf(a00, 0.0f));
                                if (ok1) __stcs(&op1[0 * NF], fmaxf(a10, 0.0f)); }
            if (j + 1 < jmax) { __stcs(&op0[1 * NF], fmaxf(a01, 0.0f));
                                if (ok1) __stcs(&op1[1 * NF], fmaxf(a11, 0.0f)); }
            if (j + 2 < jmax) { __stcs(&op0[2 * NF], fmaxf(a02, 0.0f));
                                if (ok1) __stcs(&op1[2 * NF], fmaxf(a12, 0.0f)); }
            if (j + 3 < jmax) { __stcs(&op0[3 * NF], fmaxf(a03, 0.0f));
                                if (ok1) __stcs(&op1[3 * NF], fmaxf(a13, 0.0f)); }
        }
        op0 += 4 * NF;
        op1 += 4 * NF;

        // slide window by 4: full replacement -> register rotation under unroll
        H0 = N0; H1 = N1; H2 = N2; H3 = N3;
    }
}

extern "C" void kernel_launch(void* const* d_in, const int* in_sizes, int n_in,
                              void* d_out, int out_size)
{
    const float* x    = (const float*)d_in[0];
    const float* kw   = (const float*)d_in[1];
    const float* bias = (const float*)d_in[2];
    float* out = (float*)d_out;

    dim3 grid((OHW + TC - 1) / TC,   // 8
              (OHW + TR - 1) / TR,   // 32
              BATCH);                // 32 -> 8192 blocks
    cwtconv2d_kernel<<<grid, 256>>>(x, kw, bias, out);
}

// round 14
// speedup vs baseline: 1.0523x; 1.0014x over previous
#include <cuda_runtime.h>
#include <cuda_bf16.h>

// CWTConv2D: quantized 3x3 valid conv.
// out[b,i,j,f] = relu( sum_{u,v} round(x[b,i+u,j+v]) * clip(round(kw[f,2-u,2-v]),-1,1)
//                      + round(bias[f]) )
// x (32,512,512) f32, kw (32,3,3) f32, bias (32,) f32 -> out (32,510,510,32) f32 NHWC.
//
// R14 design: warp = 2 output rows x 64 cols, lane = filter channel.
//  - tile 16 rows x 64 cols per 256-thread block; div-free float4 smem fill
//  - 2 output cols x 2 rows per inner iteration; 4-row sliding window held as
//    scalars (A,B per row), new cols loaded as one aligned LDS.64 per row
//  - register footprint ~44 (vs 62 in R13) -> launch_bounds(256,5): 62.5% occ
//  - jmax always even -> no column-tail branch in the inner loop
//  - streaming stores (__stcs): output never re-read, evict-first in L2

#define BATCH   32
#define HW      512
#define OHW     510
#define NF      32
#define TRW     2                    // output rows per warp
#define TR      16                   // output rows per block (8 warps x 2)
#define TC      64                   // output cols per block
#define SM_ROWS (TR + 2)             // 18 input rows
#define SM_STRIDE 68                 // 66 needed cols + pad; row pitch 272B (8B mult)

__global__ __launch_bounds__(256, 5)
void cwtconv2d_kernel(const float* __restrict__ x,
                      const float* __restrict__ kw,
                      const float* __restrict__ bias,
                      float* __restrict__ out)
{
    __shared__ float sx[SM_ROWS * SM_STRIDE];

    const int b   = blockIdx.z;
    const int gr0 = blockIdx.y * TR;
    const int gc0 = blockIdx.x * TC;
    const int tid  = threadIdx.x;
    const int lane = tid & 31;       // filter index
    const int wrp  = tid >> 5;

    // per-lane weights: quantize + double flip (raster-order dot with x patch)
    float wf0, wf1, wf2, wf3, wf4, wf5, wf6, wf7, wf8;
    {
        const float* kp = kw + lane * 9;
        #define QW(i) fminf(fmaxf(rintf(__ldg(&kp[8 - (i)])), -1.0f), 1.0f)
        wf0 = QW(0); wf1 = QW(1); wf2 = QW(2);
        wf3 = QW(3); wf4 = QW(4); wf5 = QW(5);
        wf6 = QW(6); wf7 = QW(7); wf8 = QW(8);
        #undef QW
    }
    const float bia = rintf(__ldg(&bias[lane]));

    // ---- div-free vectorized fill ----
    // main: 18 rows x 16 float4 tasks (cols 0..63). gc0+63 <= 511 always ->
    // only rows need guards. 288 tasks over 256 threads.
    const float* xb = x + (size_t)b * HW * HW;
    #pragma unroll
    for (int t = tid; t < SM_ROWS * 16; t += 256) {
        int r = t >> 4;
        int k = (t & 15) << 2;
        int gr = gr0 + r;
        float4 v = make_float4(0.f, 0.f, 0.f, 0.f);
        if (gr < HW)
            v = *(const float4*)&xb[gr * HW + gc0 + k];
        v.x = rintf(v.x); v.y = rintf(v.y); v.z = rintf(v.z); v.w = rintf(v.w);
        *(float4*)&sx[r * SM_STRIDE + k] = v;
    }
    // tail: tile cols 64..67 (row+col guarded; 72 threads)
    if (tid < SM_ROWS * 4) {
        int r = tid >> 2;
        int c = 64 + (tid & 3);
        int gr = gr0 + r;
        int gc = gc0 + c;
        float v = 0.0f;
        if (gr < HW && gc < HW) v = rintf(xb[gr * HW + gc]);
        sx[r * SM_STRIDE + c] = v;
    }
    __syncthreads();

    const int r0 = wrp * TRW;        // warp's first output row within tile
    const int i0 = gr0 + r0;
    const bool ok1 = (i0 + 1 < OHW);
    if (i0 >= OHW) return;

    int jmax = OHW - gc0;            // 64 except last col block: 62 (always even)
    if (jmax > TC) jmax = TC;

    const float* s0 = &sx[r0 * SM_STRIDE];

    // held window: cols j, j+1 for the 4 input rows (scalars)
    float A0 = s0[0 * SM_STRIDE], B0 = s0[0 * SM_STRIDE + 1];
    float A1 = s0[1 * SM_STRIDE], B1 = s0[1 * SM_STRIDE + 1];
    float A2 = s0[2 * SM_STRIDE], B2 = s0[2 * SM_STRIDE + 1];
    float A3 = s0[3 * SM_STRIDE], B3 = s0[3 * SM_STRIDE + 1];

    float* op0 = out + (((size_t)b * OHW + i0    ) * OHW + gc0) * NF + lane;
    float* op1 = out + (((size_t)b * OHW + i0 + 1) * OHW + gc0) * NF + lane;

    #pragma unroll 2
    for (int j = 0; j < jmax; j += 2) {
        // next 2 cols for the 4 window rows (aligned LDS.64, broadcast)
        float2 N0 = *(const float2*)&s0[0 * SM_STRIDE + j + 2];
        float2 N1 = *(const float2*)&s0[1 * SM_STRIDE + j + 2];
        float2 N2 = *(const float2*)&s0[2 * SM_STRIDE + j + 2];
        float2 N3 = *(const float2*)&s0[3 * SM_STRIDE + j + 2];

        float a00 = bia, a01 = bia;   // out row i0,   cols j, j+1
        float a10 = bia, a11 = bia;   // out row i0+1, cols j, j+1

        // out row 0 (window rows 0,1,2)
        a00 = fmaf(A0, wf0, a00); a00 = fmaf(B0, wf1, a00); a00 = fmaf(N0.x, wf2, a00);
        a01 = fmaf(B0, wf0, a01); a01 = fmaf(N0.x, wf1, a01); a01 = fmaf(N0.y, wf2, a01);
        a00 = fmaf(A1, wf3, a00); a00 = fmaf(B1, wf4, a00); a00 = fmaf(N1.x, wf5, a00);
        a01 = fmaf(B1, wf3, a01); a01 = fmaf(N1.x, wf4, a01); a01 = fmaf(N1.y, wf5, a01);
        a00 = fmaf(A2, wf6, a00); a00 = fmaf(B2, wf7, a00); a00 = fmaf(N2.x, wf8, a00);
        a01 = fmaf(B2, wf6, a01); a01 = fmaf(N2.x, wf7, a01); a01 = fmaf(N2.y, wf8, a01);

        // out row 1 (window rows 1,2,3)
        a10 = fmaf(A1, wf0, a10); a10 = fmaf(B1, wf1, a10); a10 = fmaf(N1.x, wf2, a10);
        a11 = fmaf(B1, wf0, a11); a11 = fmaf(N1.x, wf1, a11); a11 = fmaf(N1.y, wf2, a11);
        a10 = fmaf(A2, wf3, a10); a10 = fmaf(B2, wf4, a10); a10 = fmaf(N2.x, wf5, a10);
        a11 = fmaf(B2, wf3, a11); a11 = fmaf(N2.x, wf4, a11); a11 = fmaf(N2.y, wf5, a11);
        a10 = fmaf(A3, wf6, a10); a10 = fmaf(B3, wf7, a10); a10 = fmaf(N3.x, wf8, a10);
        a11 = fmaf(B3, wf6, a11); a11 = fmaf(N3.x, wf7, a11); a11 = fmaf(N3.y, wf8, a11);

        // jmax even -> both cols always valid; only row 1 needs a guard
        __stcs(&op0[0 * NF], fmaxf(a00, 0.0f));
        __stcs(&op0[1 * NF], fmaxf(a01, 0.0f));
        if (ok1) {
            __stcs(&op1[0 * NF], fmaxf(a10, 0.0f));
            __stcs(&op1[1 * NF], fmaxf(a11, 0.0f));
        }
        op0 += 2 * NF;
        op1 += 2 * NF;

        // slide window by 2: full replacement -> register rotation under unroll
        A0 = N0.x; B0 = N0.y;
        A1 = N1.x; B1 = N1.y;
        A2 = N2.x; B2 = N2.y;
        A3 = N3.x; B3 = N3.y;
    }
}

extern "C" void kernel_launch(void* const* d_in, const int* in_sizes, int n_in,
                              void* d_out, int out_size)
{
    const float* x    = (const float*)d_in[0];
    const float* kw   = (const float*)d_in[1];
    const float* bias = (const float*)d_in[2];
    float* out = (float*)d_out;

    dim3 grid((OHW + TC - 1) / TC,   // 8
              (OHW + TR - 1) / TR,   // 32
              BATCH);                // 32 -> 8192 blocks
    cwtconv2d_kernel<<<grid, 256>>>(x, kw, bias, out);
}